// round 12
// baseline (speedup 1.0000x reference)
#include <cuda_runtime.h>
#include <cuda_fp16.h>
#include <mma.h>
#include <math.h>

using namespace nvcuda;

// Problem constants (shapes fixed by the reference: [8,9,128,32,32])
#define BATCH 8
#define TT    9
#define CH    128
#define NPTS  1024
#define PAIRS 64
#define NFRAMES 72
#define NPASS 32            // init + 30 scan + final extrapolation
#define ROWBLKS 16          // 1024 rows / 64 rows per CTA

// ---------------- device scratch (static: no runtime allocation) ----------------
__device__ __half  d_Ch[67108864];        // 64*1024*1024 cost matrix in fp16 (128 MB)
__device__ __half  d_xh[NFRAMES * NPTS * CH];   // fp16 point-major copy: [frame][n][c]
__device__ float  d_sq[NFRAMES * NPTS];
__device__ float  d_chmin[CH], d_chmax[CH];
__device__ float  d_eps_pass[NPASS];
__device__ float  d_f[2][PAIRS * NPTS];   // ping-pong dual potentials
__device__ float  d_g[2][PAIRS * NPTS];
__device__ float  d_pmax[PAIRS * ROWBLKS * NPTS];  // col partial max, corrected by -g/eps (log2 units)
__device__ float  d_psum[PAIRS * ROWBLKS * NPTS];
__device__ double d_loss;

__device__ __forceinline__ float ex2f_(float x) {
    float r; asm("ex2.approx.ftz.f32 %0, %1;" : "=f"(r) : "f"(x)); return r;
}
__device__ __forceinline__ float lg2f_(float x) {
    float r; asm("lg2.approx.f32 %0, %1;" : "=f"(r) : "f"(x)); return r;
}

// padded index for gsh (stride-33 padding)
#define GP(c) ((c) + ((c) >> 5))

// ---------------- per-channel min/max over the whole sequence ----------------
__global__ void smm_minmax_kernel(const float* __restrict__ seq) {
    int c = blockIdx.x, tid = threadIdx.x;
    float mn = 3.4e38f, mx = -3.4e38f;
    for (int i = tid; i < NFRAMES * NPTS; i += 256) {
        int bt = i >> 10, n = i & 1023;
        float v = seq[((size_t)bt * CH + c) * NPTS + n];
        mn = fminf(mn, v); mx = fmaxf(mx, v);
    }
    __shared__ float smn[256], smx[256];
    smn[tid] = mn; smx[tid] = mx; __syncthreads();
    for (int s = 128; s > 0; s >>= 1) {
        if (tid < s) { smn[tid] = fminf(smn[tid], smn[tid + s]);
                       smx[tid] = fmaxf(smx[tid], smx[tid + s]); }
        __syncthreads();
    }
    if (tid == 0) { d_chmin[c] = smn[0]; d_chmax[c] = smx[0]; }
}

// ---------------- diameter -> eps annealing schedule ----------------
__global__ void smm_init_kernel() {
    int tid = threadIdx.x;
    __shared__ float red[CH];
    float dd = d_chmax[tid] - d_chmin[tid];
    red[tid] = dd * dd; __syncthreads();
    for (int s = 64; s > 0; s >>= 1) {
        if (tid < s) red[tid] += red[tid + s];
        __syncthreads();
    }
    if (tid == 0) {
        float diam = sqrtf(red[0]) + 1e-6f;
        double ld = log((double)diam);
        double lb = log(0.1);
        d_eps_pass[0] = (float)exp(2.0 * ld);
        for (int k = 0; k < 30; k++) {
            double frac = (double)k / 29.0;
            d_eps_pass[k + 1] = (float)exp(2.0 * (ld + frac * (lb - ld)));
        }
        d_eps_pass[31] = 0.01f;
        d_loss = 0.0;
    }
}

// ---------------- per-point squared norms (fp32, exact); grid (72,4) ----------------
__global__ void smm_sq_kernel(const float* __restrict__ seq) {
    int bt = blockIdx.x;
    int n = (blockIdx.y << 8) + threadIdx.x;
    const float* p = seq + (size_t)bt * CH * NPTS + n;
    float s = 0.f;
    #pragma unroll 16
    for (int c = 0; c < CH; c++) { float v = p[(size_t)c * NPTS]; s = fmaf(v, v, s); }
    d_sq[bt * NPTS + n] = s;
}

// ---------------- convert seq to fp16 point-major xh[frame][n][c]; grid (72,4) ----------------
__global__ void smm_cvt_kernel(const float* __restrict__ seq) {
    __shared__ float ts[32][65];
    int bt = blockIdx.x, qn = blockIdx.y, tid = threadIdx.x;
    const float* src = seq + (size_t)bt * CH * NPTS;
    __half* dst = d_xh + (size_t)bt * NPTS * CH;
    for (int tile = 0; tile < 16; tile++) {        // 4 c-blocks x 4 n-blocks (this quarter)
        int cb = (tile >> 2) << 5, nb = (qn << 8) + ((tile & 3) << 6);
        #pragma unroll
        for (int it = 0; it < 8; it++) {
            int idx = tid + (it << 8);
            int c = idx >> 6, n = idx & 63;
            ts[c][n] = src[(size_t)(cb + c) * NPTS + nb + n];
        }
        __syncthreads();
        #pragma unroll
        for (int it = 0; it < 4; it++) {
            int idx = tid + (it << 8);
            int n = idx >> 4, c2 = (idx & 15) << 1;
            __half2 h = __floats2half2_rn(ts[c2][n], ts[c2 + 1][n]);
            *(__half2*)&dst[(size_t)(nb + n) * CH + cb + c2] = h;
        }
        __syncthreads();
    }
}

// ---------------- cost matrix via wmma fp16 tensor cores, fp32 accumulate ----------------
// D[i][j] = x_i . y_j ; C = max(0, 0.5(sx+sy) - D), stored fp16.
// CTA 128x128 tile; 8 warps as 4(m) x 2(n); warp tile 32x64 = 2x4 wmma 16x16x16 frags.
__global__ void __launch_bounds__(256) smm_costmm_kernel() {
    __shared__ __align__(16) __half Asm[128 * 40];      // [128 rows][32 k + 8 pad]
    __shared__ __align__(16) __half Bsm[128 * 40];
    __shared__ __align__(16) float  scr[8][16 * 20];    // per-warp epilogue scratch
    __shared__ float sxs[128], sys[128];

    int p = blockIdx.z, b = p >> 3, tt = p & 7;
    int fx = b * TT + tt, fy = fx + 1;
    int i0 = blockIdx.y * 128, j0 = blockIdx.x * 128;
    int tid = threadIdx.x, w = tid >> 5, l = tid & 31;
    int wm = (w >> 1) * 32, wn = (w & 1) * 64;

    if (tid < 128) sxs[tid] = d_sq[fx * NPTS + i0 + tid];
    else           sys[tid - 128] = d_sq[fy * NPTS + j0 + tid - 128];

    wmma::fragment<wmma::accumulator, 16, 16, 16, float> acc[2][4];
    #pragma unroll
    for (int tm = 0; tm < 2; tm++)
        #pragma unroll
        for (int tn = 0; tn < 4; tn++)
            wmma::fill_fragment(acc[tm][tn], 0.0f);

    const __half* Xg = d_xh + (size_t)fx * NPTS * CH;
    const __half* Yg = d_xh + (size_t)fy * NPTS * CH;

    for (int kc = 0; kc < 4; kc++) {                    // k chunks of 32
        int k0 = kc * 32;
        #pragma unroll
        for (int q = 0; q < 2; q++) {
            int u = tid + (q << 8);
            int row = u >> 2, c8 = (u & 3) << 3;
            *(uint4*)&Asm[row * 40 + c8] = *(const uint4*)&Xg[(size_t)(i0 + row) * CH + k0 + c8];
            *(uint4*)&Bsm[row * 40 + c8] = *(const uint4*)&Yg[(size_t)(j0 + row) * CH + k0 + c8];
        }
        __syncthreads();
        #pragma unroll
        for (int ks = 0; ks < 2; ks++) {
            wmma::fragment<wmma::matrix_a, 16, 16, 16, __half, wmma::row_major> af[2];
            wmma::fragment<wmma::matrix_b, 16, 16, 16, __half, wmma::col_major> bf[4];
            #pragma unroll
            for (int tm = 0; tm < 2; tm++)
                wmma::load_matrix_sync(af[tm], &Asm[(wm + tm * 16) * 40 + ks * 16], 40);
            #pragma unroll
            for (int tn = 0; tn < 4; tn++)
                wmma::load_matrix_sync(bf[tn], &Bsm[(wn + tn * 16) * 40 + ks * 16], 40);
            #pragma unroll
            for (int tm = 0; tm < 2; tm++)
                #pragma unroll
                for (int tn = 0; tn < 4; tn++)
                    wmma::mma_sync(acc[tm][tn], af[tm], bf[tn], acc[tm][tn]);
        }
        __syncthreads();
    }

    __half* Co = d_Ch + (size_t)p * NPTS * NPTS;
    int r = l >> 1, cb = (l & 1) << 3;
    #pragma unroll
    for (int tm = 0; tm < 2; tm++) {
        #pragma unroll
        for (int tn = 0; tn < 4; tn++) {
            wmma::store_matrix_sync(&scr[w][0], acc[tm][tn], 20, wmma::mem_row_major);
            __syncwarp();
            float sx = sxs[wm + tm * 16 + r];
            union { uint4 u4; __half2 h[4]; } pk;
            #pragma unroll
            for (int j = 0; j < 4; j++) {
                int c = cb + j * 2;
                float d0 = scr[w][r * 20 + c], d1 = scr[w][r * 20 + c + 1];
                float v0 = fmaxf(0.5f * (sx + sys[wn + tn * 16 + c]) - d0, 0.f);
                float v1 = fmaxf(0.5f * (sx + sys[wn + tn * 16 + c + 1]) - d1, 0.f);
                pk.h[j] = __floats2half2_rn(v0, v1);
            }
            *(uint4*)&Co[(size_t)(i0 + wm + tm * 16 + r) * NPTS + j0 + wn + tn * 16 + cb] = pk.u4;
            __syncwarp();
        }
    }
}

// ---------------- fused Sinkhorn sweep (fp16 C, half2 exp, g folded at load) ----------------
// flags: bit0 zero-init pass, bit1 average f-update, bit2 final (loss) pass.
__global__ void __launch_bounds__(256, 2) smm_sink_kernel(int pass, int flags) {
    __shared__ float Cs[128 * 65];        // col-major (col*65 + r), holds x = (g - C)/eps in log2 units
    __shared__ float gsh[1056];           // g * log2e/eps, padded GP()
    __shared__ float fsh[64];
    __shared__ float fraw[64];
    __shared__ float red[256];
    int p = blockIdx.y, rb = blockIdx.x, tid = threadIdx.x;
    int zf = flags & 1, avg = flags & 2, fin = flags & 4;
    float eps = d_eps_pass[pass];
    float ivl = 1.4426950408889634f / eps;
    float nivl = -ivl;
    int r0 = rb * 64;
    const float* f_in = d_f[pass & 1];
    const float* g_in = d_g[pass & 1];
    float* f_out = d_f[(pass + 1) & 1];

    for (int j = tid; j < 1024; j += 256) gsh[GP(j)] = zf ? 0.f : g_in[p * 1024 + j] * ivl;
    if (tid < 64) {
        float fv = zf ? 0.f : f_in[p * 1024 + r0 + tid];
        fraw[tid] = fv; fsh[tid] = fv * ivl;
    }
    __syncthreads();

    int row = tid >> 2, part = tid & 3;      // row sweep: 64 rows x 4 lanes
    int ccol = tid >> 1, chalf = tid & 1;    // col sweep: 128 cols x 2 lanes
    float rm = -1e30f, rs = 0.f;
    const __half2* Cp2 = (const __half2*)d_Ch + (size_t)p * 524288 + (size_t)r0 * 512;

    for (int t8 = 0; t8 < 8; t8++) {
        int c0 = t8 << 7;
        // ---- load 64x128 tile (streaming: keep partials/f/g in L2, not C) ----
        #pragma unroll
        for (int q = 0; q < 16; q++) {
            int idx2 = tid + (q << 8);
            int r = idx2 >> 6, c2 = idx2 & 63;
            unsigned cu = __ldcs((const unsigned*)&Cp2[(size_t)r * 512 + (c0 >> 1) + c2]);
            float2 fv = __half22float2(*(__half2*)&cu);
            int col = c2 << 1;
            Cs[col * 65 + r]       = fmaf(fv.x, nivl, gsh[GP(c0 + col)]);
            Cs[(col + 1) * 65 + r] = fmaf(fv.y, nivl, gsh[GP(c0 + col + 1)]);
        }
        __syncthreads();
        // ---- row direction: two 16-chunks, half2 exp, online max/sum merge ----
        #pragma unroll
        for (int h = 0; h < 2; h++) {
            float v16[16]; float lm = -1e30f;
            #pragma unroll
            for (int k = 0; k < 16; k++) {
                int cc = (part << 5) + ((k + (h << 4) + (part << 3)) & 31);
                float x = Cs[cc * 65 + row];
                v16[k] = x; lm = fmaxf(lm, x);
            }
            lm = fmaxf(lm, __shfl_xor_sync(0xffffffffu, lm, 1));
            lm = fmaxf(lm, __shfl_xor_sync(0xffffffffu, lm, 2));
            float nm = fmaxf(rm, lm);
            __half2 hacc = __floats2half2_rn(0.f, 0.f);
            #pragma unroll
            for (int k = 0; k < 16; k += 2)
                hacc = __hadd2(hacc, h2exp2(__floats2half2_rn(v16[k] - nm, v16[k + 1] - nm)));
            float2 e2 = __half22float2(hacc);
            float ls = e2.x + e2.y;
            ls += __shfl_xor_sync(0xffffffffu, ls, 1);
            ls += __shfl_xor_sync(0xffffffffu, ls, 2);
            rs = rs * ex2f_(rm - nm) + ls; rm = nm;
        }
        // ---- column direction: two 16-chunks per lane-pair, half2 exp ----
        float cm = -1e30f, cs_ = 0.f;
        #pragma unroll
        for (int h = 0; h < 2; h++) {
            float w16[16]; float lm = -1e30f;
            #pragma unroll
            for (int k = 0; k < 16; k++) {
                int rr = (chalf << 5) + ((k + (h << 4) + (chalf << 4)) & 31);
                float v = Cs[ccol * 65 + rr] + fsh[rr];
                w16[k] = v; lm = fmaxf(lm, v);
            }
            float nm = fmaxf(cm, lm);
            __half2 hacc = __floats2half2_rn(0.f, 0.f);
            #pragma unroll
            for (int k = 0; k < 16; k += 2)
                hacc = __hadd2(hacc, h2exp2(__floats2half2_rn(w16[k] - nm, w16[k + 1] - nm)));
            float2 e2 = __half22float2(hacc);
            cs_ = cs_ * ex2f_(cm - nm) + (e2.x + e2.y); cm = nm;
        }
        float cmx = fmaxf(cm, __shfl_xor_sync(0xffffffffu, cm, 1));
        float cls = cs_ * ex2f_(cm - cmx);
        cls += __shfl_xor_sync(0xffffffffu, cls, 1);
        if (chalf == 0) {
            int o = (p * ROWBLKS + rb) * 1024 + c0 + ccol;
            d_pmax[o] = cmx - gsh[GP(c0 + ccol)];   // correct to (f - C)/eps units
            d_psum[o] = cls;
        }
        __syncthreads();
    }
    float ft = -eps * 0.69314718055994531f * (rm + lg2f_(rs) - 10.f);
    if (!fin) {
        if (part == 0) f_out[p * 1024 + r0 + row] = avg ? 0.5f * (fraw[row] + ft) : ft;
    } else {
        red[tid] = (part == 0) ? ft : 0.f;
        __syncthreads();
        for (int s = 128; s > 0; s >>= 1) {
            if (tid < s) red[tid] += red[tid + s];
            __syncthreads();
        }
        if (tid == 0) atomicAdd(&d_loss, (double)red[0]);
    }
}

// ---------------- merge 16 row-strip column partials -> gt_j ----------------
__global__ void smm_combine_kernel(int pass, int flags) {
    int gid = blockIdx.x * 256 + threadIdx.x;
    int p = gid >> 10, col = gid & 1023;
    const float* g_in = d_g[pass & 1];
    float* g_out = d_g[(pass + 1) & 1];
    int avg = flags & 2, fin = flags & 4;
    float eps = d_eps_pass[pass];
    float M = -1e30f;
    float pm[ROWBLKS];
    #pragma unroll
    for (int b2 = 0; b2 < ROWBLKS; b2++) {
        pm[b2] = d_pmax[(p * ROWBLKS + b2) * 1024 + col];
        M = fmaxf(M, pm[b2]);
    }
    float S = 0.f;
    #pragma unroll
    for (int b2 = 0; b2 < ROWBLKS; b2++)
        S += d_psum[(p * ROWBLKS + b2) * 1024 + col] * ex2f_(pm[b2] - M);
    float gt = -eps * 0.69314718055994531f * (M + lg2f_(S) - 10.f);
    if (!fin) {
        g_out[gid] = avg ? 0.5f * (g_in[gid] + gt) : gt;
    } else {
        __shared__ float red[256];
        red[threadIdx.x] = gt; __syncthreads();
        for (int s = 128; s > 0; s >>= 1) {
            if (threadIdx.x < s) red[threadIdx.x] += red[threadIdx.x + s];
            __syncthreads();
        }
        if (threadIdx.x == 0) atomicAdd(&d_loss, (double)red[0]);
    }
}

__global__ void smm_finalize_kernel(float* out, int n) {
    float v = (float)(d_loss * (1.0 / 65536.0));   // /(P*N)
    for (int i = threadIdx.x; i < n; i += 32) out[i] = v;
}

// ---------------- launch: graph-capturable, no allocs, no sync ----------------
extern "C" void kernel_launch(void* const* d_in, const int* in_sizes, int n_in,
                              void* d_out, int out_size) {
    const float* seq = (const float*)d_in[0];
    smm_minmax_kernel<<<CH, 256>>>(seq);
    smm_init_kernel<<<1, CH>>>();
    smm_sq_kernel<<<dim3(NFRAMES, 4), 256>>>(seq);
    smm_cvt_kernel<<<dim3(NFRAMES, 4), 256>>>(seq);
    smm_costmm_kernel<<<dim3(8, 8, PAIRS), 256>>>();
    for (int pass = 0; pass < NPASS; ++pass) {
        int flags = (pass == 0 ? 1 : 0)
                  | ((pass >= 1 && pass <= 30) ? 2 : 0)
                  | (pass == 31 ? 4 : 0);
        smm_sink_kernel<<<dim3(ROWBLKS, PAIRS), 256>>>(pass, flags);
        smm_combine_kernel<<<PAIRS * NPTS / 256, 256>>>(pass, flags);
    }
    smm_finalize_kernel<<<1, 32>>>((float*)d_out, out_size);
}

// round 14
// speedup vs baseline: 1.6274x; 1.6274x over previous
#include <cuda_runtime.h>
#include <cuda_fp16.h>
#include <mma.h>
#include <math.h>
#include <stdint.h>

using namespace nvcuda;

// Problem constants (shapes fixed by the reference: [8,9,128,32,32])
#define BATCH 8
#define TT    9
#define CH    128
#define NPTS  1024
#define PAIRS 64
#define NFRAMES 72
#define NPASS 32            // init + 30 scan + final extrapolation
#define ROWBLKS 16          // 1024 rows / 64 rows per CTA

// ---------------- device scratch (static: no runtime allocation) ----------------
__device__ __half  d_Ch[67108864];        // 64*1024*1024 cost matrix in fp16 (128 MB)
__device__ __half  d_xh[NFRAMES * NPTS * CH];   // fp16 point-major copy: [frame][n][c]
__device__ float  d_sq[NFRAMES * NPTS];
__device__ float  d_chmin[CH], d_chmax[CH];
__device__ float  d_eps_pass[NPASS];
__device__ float  d_f[2][PAIRS * NPTS];   // ping-pong dual potentials
__device__ float  d_g[2][PAIRS * NPTS];
__device__ float  d_pmax[PAIRS * ROWBLKS * NPTS];  // col partial max, corrected by -g/eps (log2 units)
__device__ float  d_psum[PAIRS * ROWBLKS * NPTS];
__device__ double d_loss;

__device__ __forceinline__ float ex2f_(float x) {
    float r; asm("ex2.approx.ftz.f32 %0, %1;" : "=f"(r) : "f"(x)); return r;
}
__device__ __forceinline__ float lg2f_(float x) {
    float r; asm("lg2.approx.f32 %0, %1;" : "=f"(r) : "f"(x)); return r;
}
__device__ __forceinline__ void cp16(unsigned int dst, const void* src) {
    asm volatile("cp.async.cg.shared.global [%0], [%1], 16;" :: "r"(dst), "l"(src) : "memory");
}

// padded index for gsh (stride-33 padding)
#define GP(c) ((c) + ((c) >> 5))

// ---------------- per-channel min/max over the whole sequence ----------------
__global__ void smm_minmax_kernel(const float* __restrict__ seq) {
    int c = blockIdx.x, tid = threadIdx.x;
    float mn = 3.4e38f, mx = -3.4e38f;
    for (int i = tid; i < NFRAMES * NPTS; i += 256) {
        int bt = i >> 10, n = i & 1023;
        float v = seq[((size_t)bt * CH + c) * NPTS + n];
        mn = fminf(mn, v); mx = fmaxf(mx, v);
    }
    __shared__ float smn[256], smx[256];
    smn[tid] = mn; smx[tid] = mx; __syncthreads();
    for (int s = 128; s > 0; s >>= 1) {
        if (tid < s) { smn[tid] = fminf(smn[tid], smn[tid + s]);
                       smx[tid] = fmaxf(smx[tid], smx[tid + s]); }
        __syncthreads();
    }
    if (tid == 0) { d_chmin[c] = smn[0]; d_chmax[c] = smx[0]; }
}

// ---------------- diameter -> eps annealing schedule ----------------
__global__ void smm_init_kernel() {
    int tid = threadIdx.x;
    __shared__ float red[CH];
    float dd = d_chmax[tid] - d_chmin[tid];
    red[tid] = dd * dd; __syncthreads();
    for (int s = 64; s > 0; s >>= 1) {
        if (tid < s) red[tid] += red[tid + s];
        __syncthreads();
    }
    if (tid == 0) {
        float diam = sqrtf(red[0]) + 1e-6f;
        double ld = log((double)diam);
        double lb = log(0.1);
        d_eps_pass[0] = (float)exp(2.0 * ld);
        for (int k = 0; k < 30; k++) {
            double frac = (double)k / 29.0;
            d_eps_pass[k + 1] = (float)exp(2.0 * (ld + frac * (lb - ld)));
        }
        d_eps_pass[31] = 0.01f;
        d_loss = 0.0;
    }
}

// ---------------- per-point squared norms (fp32, exact); grid (72,4) ----------------
__global__ void smm_sq_kernel(const float* __restrict__ seq) {
    int bt = blockIdx.x;
    int n = (blockIdx.y << 8) + threadIdx.x;
    const float* p = seq + (size_t)bt * CH * NPTS + n;
    float s = 0.f;
    #pragma unroll 16
    for (int c = 0; c < CH; c++) { float v = p[(size_t)c * NPTS]; s = fmaf(v, v, s); }
    d_sq[bt * NPTS + n] = s;
}

// ---------------- convert seq to fp16 point-major xh[frame][n][c]; grid (72,4) ----------------
__global__ void smm_cvt_kernel(const float* __restrict__ seq) {
    __shared__ float ts[32][65];
    int bt = blockIdx.x, qn = blockIdx.y, tid = threadIdx.x;
    const float* src = seq + (size_t)bt * CH * NPTS;
    __half* dst = d_xh + (size_t)bt * NPTS * CH;
    for (int tile = 0; tile < 16; tile++) {
        int cb = (tile >> 2) << 5, nb = (qn << 8) + ((tile & 3) << 6);
        #pragma unroll
        for (int it = 0; it < 8; it++) {
            int idx = tid + (it << 8);
            int c = idx >> 6, n = idx & 63;
            ts[c][n] = src[(size_t)(cb + c) * NPTS + nb + n];
        }
        __syncthreads();
        #pragma unroll
        for (int it = 0; it < 4; it++) {
            int idx = tid + (it << 8);
            int n = idx >> 4, c2 = (idx & 15) << 1;
            __half2 h = __floats2half2_rn(ts[c2][n], ts[c2 + 1][n]);
            *(__half2*)&dst[(size_t)(nb + n) * CH + cb + c2] = h;
        }
        __syncthreads();
    }
}

// ---------------- cost matrix via wmma fp16 tensor cores, fp32 accumulate ----------------
__global__ void __launch_bounds__(256) smm_costmm_kernel() {
    __shared__ __align__(16) __half Asm[128 * 40];
    __shared__ __align__(16) __half Bsm[128 * 40];
    __shared__ __align__(16) float  scr[8][16 * 20];
    __shared__ float sxs[128], sys[128];

    int p = blockIdx.z, b = p >> 3, tt = p & 7;
    int fx = b * TT + tt, fy = fx + 1;
    int i0 = blockIdx.y * 128, j0 = blockIdx.x * 128;
    int tid = threadIdx.x, w = tid >> 5, l = tid & 31;
    int wm = (w >> 1) * 32, wn = (w & 1) * 64;

    if (tid < 128) sxs[tid] = d_sq[fx * NPTS + i0 + tid];
    else           sys[tid - 128] = d_sq[fy * NPTS + j0 + tid - 128];

    wmma::fragment<wmma::accumulator, 16, 16, 16, float> acc[2][4];
    #pragma unroll
    for (int tm = 0; tm < 2; tm++)
        #pragma unroll
        for (int tn = 0; tn < 4; tn++)
            wmma::fill_fragment(acc[tm][tn], 0.0f);

    const __half* Xg = d_xh + (size_t)fx * NPTS * CH;
    const __half* Yg = d_xh + (size_t)fy * NPTS * CH;

    for (int kc = 0; kc < 4; kc++) {
        int k0 = kc * 32;
        #pragma unroll
        for (int q = 0; q < 2; q++) {
            int u = tid + (q << 8);
            int row = u >> 2, c8 = (u & 3) << 3;
            *(uint4*)&Asm[row * 40 + c8] = *(const uint4*)&Xg[(size_t)(i0 + row) * CH + k0 + c8];
            *(uint4*)&Bsm[row * 40 + c8] = *(const uint4*)&Yg[(size_t)(j0 + row) * CH + k0 + c8];
        }
        __syncthreads();
        #pragma unroll
        for (int ks = 0; ks < 2; ks++) {
            wmma::fragment<wmma::matrix_a, 16, 16, 16, __half, wmma::row_major> af[2];
            wmma::fragment<wmma::matrix_b, 16, 16, 16, __half, wmma::col_major> bf[4];
            #pragma unroll
            for (int tm = 0; tm < 2; tm++)
                wmma::load_matrix_sync(af[tm], &Asm[(wm + tm * 16) * 40 + ks * 16], 40);
            #pragma unroll
            for (int tn = 0; tn < 4; tn++)
                wmma::load_matrix_sync(bf[tn], &Bsm[(wn + tn * 16) * 40 + ks * 16], 40);
            #pragma unroll
            for (int tm = 0; tm < 2; tm++)
                #pragma unroll
                for (int tn = 0; tn < 4; tn++)
                    wmma::mma_sync(acc[tm][tn], af[tm], bf[tn], acc[tm][tn]);
        }
        __syncthreads();
    }

    __half* Co = d_Ch + (size_t)p * NPTS * NPTS;
    int r = l >> 1, cb = (l & 1) << 3;
    #pragma unroll
    for (int tm = 0; tm < 2; tm++) {
        #pragma unroll
        for (int tn = 0; tn < 4; tn++) {
            wmma::store_matrix_sync(&scr[w][0], acc[tm][tn], 20, wmma::mem_row_major);
            __syncwarp();
            float sx = sxs[wm + tm * 16 + r];
            union { uint4 u4; __half2 h[4]; } pk;
            #pragma unroll
            for (int j = 0; j < 4; j++) {
                int c = cb + j * 2;
                float d0 = scr[w][r * 20 + c], d1 = scr[w][r * 20 + c + 1];
                float v0 = fmaxf(0.5f * (sx + sys[wn + tn * 16 + c]) - d0, 0.f);
                float v1 = fmaxf(0.5f * (sx + sys[wn + tn * 16 + c + 1]) - d1, 0.f);
                pk.h[j] = __floats2half2_rn(v0, v1);
            }
            *(uint4*)&Co[(size_t)(i0 + wm + tm * 16 + r) * NPTS + j0 + wn + tn * 16 + cb] = pk.u4;
            __syncwarp();
        }
    }
}

// ---------------- fused Sinkhorn sweep: cp.async double-buffered fp16 tiles ----------------
// Staging ring st[2]: 64 rows x 128 cols fp16, row stride 136 halfs (272B, 16B-aligned).
// Row dir: half2 + FMA (g folded); col dir: half extract + FMA (gI hoisted, pmax -= gI).
// flags: bit0 zero-init pass, bit1 average f-update, bit2 final (loss) pass.
__global__ void __launch_bounds__(256, 2) smm_sink_kernel(int pass, int flags) {
    __shared__ __align__(16) __half st[2][64 * 136];
    __shared__ float gsh[1056];           // g * log2e/eps, padded GP()
    __shared__ float fsh[64];
    __shared__ float fraw[64];
    __shared__ float red[256];
    int p = blockIdx.y, rb = blockIdx.x, tid = threadIdx.x;
    int zf = flags & 1, avg = flags & 2, fin = flags & 4;
    float eps = d_eps_pass[pass];
    float ivl = 1.4426950408889634f / eps;
    float nivl = -ivl;
    int r0 = rb * 64;
    const float* f_in = d_f[pass & 1];
    const float* g_in = d_g[pass & 1];
    float* f_out = d_f[(pass + 1) & 1];

    const __half* Cph = d_Ch + (size_t)p * 1048576 + (size_t)r0 * 1024;
    unsigned int stb = (unsigned int)__cvta_generic_to_shared(&st[0][0]);

    // issue tile 0 into buffer 0 (4 x 16B per thread)
    #pragma unroll
    for (int q = 0; q < 4; q++) {
        int id = (q << 8) + tid, r = id >> 4, j8 = id & 15;
        cp16(stb + r * 272 + (j8 << 4), Cph + (size_t)r * 1024 + (j8 << 3));
    }
    asm volatile("cp.async.commit_group;" ::: "memory");

    for (int j = tid; j < 1024; j += 256) gsh[GP(j)] = zf ? 0.f : g_in[p * 1024 + j] * ivl;
    if (tid < 64) {
        float fv = zf ? 0.f : f_in[p * 1024 + r0 + tid];
        fraw[tid] = fv; fsh[tid] = fv * ivl;
    }

    int row = tid >> 2, part = tid & 3;      // row sweep: 64 rows x 4 lanes
    int ccol = tid >> 1, chalf = tid & 1;    // col sweep: 128 cols x 2 lanes
    float rm = -1e30f, rs = 0.f;

    for (int t8 = 0; t8 < 8; t8++) {
        int c0 = t8 << 7;
        if (t8 < 7) {   // prefetch next tile into the other buffer
            int nb = (t8 + 1) & 1;
            #pragma unroll
            for (int q = 0; q < 4; q++) {
                int id = (q << 8) + tid, r = id >> 4, j8 = id & 15;
                cp16(stb + nb * 17408 + r * 272 + (j8 << 4),
                     Cph + (size_t)r * 1024 + c0 + 128 + (j8 << 3));
            }
            asm volatile("cp.async.commit_group;" ::: "memory");
            asm volatile("cp.async.wait_group 1;" ::: "memory");
        } else {
            asm volatile("cp.async.wait_group 0;" ::: "memory");
        }
        __syncthreads();   // staged tile t8 visible (also orders gsh/fsh on t8=0)

        const __half2* S = (const __half2*)&st[t8 & 1][0];   // row stride 68 words
        // ---- row direction: two 16-chunks, online max/sum merge ----
        #pragma unroll
        for (int h = 0; h < 2; h++) {
            float v16[16]; float lm = -1e30f;
            #pragma unroll
            for (int q = 0; q < 8; q++) {
                int qr = (q + (part << 1)) & 7;                 // phase rotation
                int h2i = (part << 4) + (h << 3) + qr;          // half2 idx in row
                float2 cv = __half22float2(S[row * 68 + h2i]);
                int colp = c0 + (h2i << 1);
                float x0 = fmaf(cv.x, nivl, gsh[GP(colp)]);
                float x1 = fmaf(cv.y, nivl, gsh[GP(colp + 1)]);
                v16[q * 2] = x0; v16[q * 2 + 1] = x1;
                lm = fmaxf(lm, fmaxf(x0, x1));
            }
            lm = fmaxf(lm, __shfl_xor_sync(0xffffffffu, lm, 1));
            lm = fmaxf(lm, __shfl_xor_sync(0xffffffffu, lm, 2));
            float nm = fmaxf(rm, lm);
            float ls = 0.f;
            #pragma unroll
            for (int k = 0; k < 16; k++) ls += ex2f_(v16[k] - nm);
            ls += __shfl_xor_sync(0xffffffffu, ls, 1);
            ls += __shfl_xor_sync(0xffffffffu, ls, 2);
            rs = rs * ex2f_(rm - nm) + ls; rm = nm;
        }
        // ---- column direction: two 16-chunks per lane-pair ----
        float gI = gsh[GP(c0 + ccol)];
        const unsigned int* Sw = (const unsigned int*)S;
        float cm = -1e30f, cs_ = 0.f;
        #pragma unroll
        for (int h = 0; h < 2; h++) {
            float w16[16]; float lm = -1e30f;
            #pragma unroll
            for (int k = 0; k < 16; k++) {
                int rr = (chalf << 5) + (((h << 4) + k + (chalf << 3)) & 31);
                unsigned int wv = Sw[rr * 68 + (ccol >> 1)];
                unsigned short hs = (ccol & 1) ? (unsigned short)(wv >> 16)
                                               : (unsigned short)(wv & 0xffffu);
                float v = fmaf(__half2float(__ushort_as_half(hs)), nivl, gI + fsh[rr]);
                w16[k] = v; lm = fmaxf(lm, v);
            }
            float nm = fmaxf(cm, lm);
            float ls = 0.f;
            #pragma unroll
            for (int k = 0; k < 16; k++) ls += ex2f_(w16[k] - nm);
            cs_ = cs_ * ex2f_(cm - nm) + ls; cm = nm;
        }
        float cmx = fmaxf(cm, __shfl_xor_sync(0xffffffffu, cm, 1));
        float cls = cs_ * ex2f_(cm - cmx);
        cls += __shfl_xor_sync(0xffffffffu, cls, 1);
        if (chalf == 0) {
            int o = (p * ROWBLKS + rb) * 1024 + c0 + ccol;
            d_pmax[o] = cmx - gI;     // correct to (f - C)/eps units
            d_psum[o] = cls;
        }
        __syncthreads();   // all reads of buffer t8&1 done before it is refilled
    }
    float ft = -eps * 0.69314718055994531f * (rm + lg2f_(rs) - 10.f);
    if (!fin) {
        if (part == 0) f_out[p * 1024 + r0 + row] = avg ? 0.5f * (fraw[row] + ft) : ft;
    } else {
        red[tid] = (part == 0) ? ft : 0.f;
        __syncthreads();
        for (int s = 128; s > 0; s >>= 1) {
            if (tid < s) red[tid] += red[tid + s];
            __syncthreads();
        }
        if (tid == 0) atomicAdd(&d_loss, (double)red[0]);
    }
}

// ---------------- merge 16 row-strip column partials -> gt_j ----------------
__global__ void smm_combine_kernel(int pass, int flags) {
    int gid = blockIdx.x * 256 + threadIdx.x;
    int p = gid >> 10, col = gid & 1023;
    const float* g_in = d_g[pass & 1];
    float* g_out = d_g[(pass + 1) & 1];
    int avg = flags & 2, fin = flags & 4;
    float eps = d_eps_pass[pass];
    float M = -1e30f;
    float pm[ROWBLKS];
    #pragma unroll
    for (int b2 = 0; b2 < ROWBLKS; b2++) {
        pm[b2] = d_pmax[(p * ROWBLKS + b2) * 1024 + col];
        M = fmaxf(M, pm[b2]);
    }
    float S = 0.f;
    #pragma unroll
    for (int b2 = 0; b2 < ROWBLKS; b2++)
        S += d_psum[(p * ROWBLKS + b2) * 1024 + col] * ex2f_(pm[b2] - M);
    float gt = -eps * 0.69314718055994531f * (M + lg2f_(S) - 10.f);
    if (!fin) {
        g_out[gid] = avg ? 0.5f * (g_in[gid] + gt) : gt;
    } else {
        __shared__ float red[256];
        red[threadIdx.x] = gt; __syncthreads();
        for (int s = 128; s > 0; s >>= 1) {
            if (threadIdx.x < s) red[threadIdx.x] += red[threadIdx.x + s];
            __syncthreads();
        }
        if (threadIdx.x == 0) atomicAdd(&d_loss, (double)red[0]);
    }
}

__global__ void smm_finalize_kernel(float* out, int n) {
    float v = (float)(d_loss * (1.0 / 65536.0));   // /(P*N)
    for (int i = threadIdx.x; i < n; i += 32) out[i] = v;
}

// ---------------- launch: graph-capturable, no allocs, no sync ----------------
extern "C" void kernel_launch(void* const* d_in, const int* in_sizes, int n_in,
                              void* d_out, int out_size) {
    const float* seq = (const float*)d_in[0];
    smm_minmax_kernel<<<CH, 256>>>(seq);
    smm_init_kernel<<<1, CH>>>();
    smm_sq_kernel<<<dim3(NFRAMES, 4), 256>>>(seq);
    smm_cvt_kernel<<<dim3(NFRAMES, 4), 256>>>(seq);
    smm_costmm_kernel<<<dim3(8, 8, PAIRS), 256>>>();
    for (int pass = 0; pass < NPASS; ++pass) {
        int flags = (pass == 0 ? 1 : 0)
                  | ((pass >= 1 && pass <= 30) ? 2 : 0)
                  | (pass == 31 ? 4 : 0);
        smm_sink_kernel<<<dim3(ROWBLKS, PAIRS), 256>>>(pass, flags);
        smm_combine_kernel<<<PAIRS * NPTS / 256, 256>>>(pass, flags);
    }
    smm_finalize_kernel<<<1, 32>>>((float*)d_out, out_size);
}